// round 15
// baseline (speedup 1.0000x reference)
#include <cuda_runtime.h>
#include <cuda_fp16.h>
#include <math.h>
#include <stdint.h>

#define Bdim 256
#define Jdim 64
#define Ddim 512

// ---- scratch (allocation-free rule: __device__ globals) ----
__device__ float g_Q[Bdim * Ddim];     // inputs @ W
__device__ float g_P[Jdim * Ddim];     // keys @ V + U_bias
// U pre-split fp16, transposed, k16-interleaved:
// g_UH[(col*32 + s)*4 + tg] = { hi2(16s+2tg,+1), hi2(16s+2tg+8,+9),
//                               lo2(16s+2tg,+1), lo2(16s+2tg+8,+9) }
__device__ uint4 g_UH[Ddim * 32 * 4];

// ---------------- cp.async helpers ----------------
__device__ __forceinline__ void cp_async16(void* smem_dst, const void* gmem_src) {
    unsigned s = (unsigned)__cvta_generic_to_shared(smem_dst);
    asm volatile("cp.async.cg.shared.global [%0], [%1], 16;\n" :: "r"(s), "l"(gmem_src));
}
__device__ __forceinline__ void cp_commit() { asm volatile("cp.async.commit_group;\n"); }
__device__ __forceinline__ void cp_wait2()  { asm volatile("cp.async.wait_group 2;\n"); }
__device__ __forceinline__ void cp_wait1()  { asm volatile("cp.async.wait_group 1;\n"); }
__device__ __forceinline__ void cp_wait0()  { asm volatile("cp.async.wait_group 0;\n"); }

// ---------------- fp16 split helpers ----------------
__device__ __forceinline__ void split_h(float x, unsigned short& hi, unsigned short& lo) {
    __half h = __float2half_rn(x);
    hi = __half_as_ushort(h);
    lo = __half_as_ushort(__float2half_rn(x - __half2float(h)));
}
__device__ __forceinline__ unsigned pack2(unsigned short a, unsigned short b) {
    return (unsigned)a | ((unsigned)b << 16);
}
// packed split of a float pair -> (hi2, lo2) as uints
__device__ __forceinline__ void split2(float x, float y, unsigned& hi2, unsigned& lo2) {
    __half2 h = __floats2half2_rn(x, y);
    float rx = x - __low2float(h);
    float ry = y - __high2float(h);
    __half2 l = __floats2half2_rn(rx, ry);
    hi2 = *reinterpret_cast<unsigned*>(&h);
    lo2 = *reinterpret_cast<unsigned*>(&l);
}
// D += A(16x16,row) * B(16x8,col)   (fp16 in, fp32 acc)
__device__ __forceinline__ void mma_f16(float d[4], const unsigned a[4], unsigned b0, unsigned b1) {
    asm volatile("mma.sync.aligned.m16n8k16.row.col.f32.f16.f16.f32 "
        "{%0,%1,%2,%3}, {%4,%5,%6,%7}, {%8,%9}, {%0,%1,%2,%3};"
        : "+f"(d[0]), "+f"(d[1]), "+f"(d[2]), "+f"(d[3])
        : "r"(a[0]), "r"(a[1]), "r"(a[2]), "r"(a[3]), "r"(b0), "r"(b1));
}

// ---------------- precompute ----------------
__device__ __forceinline__ void sgemm_tile_body(
    const float* __restrict__ A, const float* __restrict__ Bm,
    const float* __restrict__ bias, float* __restrict__ C,
    int m0, int n0, int N, int K,
    float (*As)[64], float (*Bs)[64])
{
    int tid = threadIdx.x;
    int ty = tid >> 4, tx = tid & 15;
    float acc[4][4];
#pragma unroll
    for (int i = 0; i < 4; i++)
#pragma unroll
        for (int j = 0; j < 4; j++) acc[i][j] = 0.f;
    for (int k0 = 0; k0 < K; k0 += 16) {
        {
            int m = tid >> 2, kk = (tid & 3) * 4;
            float4 v = *reinterpret_cast<const float4*>(&A[(size_t)(m0 + m) * K + k0 + kk]);
            As[kk + 0][m] = v.x; As[kk + 1][m] = v.y;
            As[kk + 2][m] = v.z; As[kk + 3][m] = v.w;
        }
        {
            int kk = tid >> 4, c4 = (tid & 15) * 4;
            *reinterpret_cast<float4*>(&Bs[kk][c4]) =
                *reinterpret_cast<const float4*>(&Bm[(size_t)(k0 + kk) * N + n0 + c4]);
        }
        __syncthreads();
#pragma unroll
        for (int kk = 0; kk < 16; kk++) {
            float4 a4 = *reinterpret_cast<const float4*>(&As[kk][ty * 4]);
            float4 b4 = *reinterpret_cast<const float4*>(&Bs[kk][tx * 4]);
            float a[4] = {a4.x, a4.y, a4.z, a4.w};
            float b[4] = {b4.x, b4.y, b4.z, b4.w};
#pragma unroll
            for (int i = 0; i < 4; i++)
#pragma unroll
                for (int j = 0; j < 4; j++) acc[i][j] += a[i] * b[j];
        }
        __syncthreads();
    }
    float bx = 0.f, by = 0.f, bz = 0.f, bw = 0.f;
    if (bias) {
        bx = bias[n0 + tx * 4 + 0]; by = bias[n0 + tx * 4 + 1];
        bz = bias[n0 + tx * 4 + 2]; bw = bias[n0 + tx * 4 + 3];
    }
#pragma unroll
    for (int i = 0; i < 4; i++) {
        float4 o;
        o.x = acc[i][0] + bx; o.y = acc[i][1] + by;
        o.z = acc[i][2] + bz; o.w = acc[i][3] + bw;
        *reinterpret_cast<float4*>(&C[(size_t)(m0 + ty * 4 + i) * N + n0 + tx * 4]) = o;
    }
}

// blocks: [0,32) Q ; [32,40) P ; [40,104) UH
__global__ __launch_bounds__(256) void precompute_kernel(
    const float* __restrict__ inputs, const float* __restrict__ keys,
    const float* __restrict__ V, const float* __restrict__ W,
    const float* __restrict__ U, const float* __restrict__ Ubias)
{
    __shared__ float As[16][64];
    __shared__ float Bs[16][64];
    int bx = blockIdx.x, tid = threadIdx.x;
    if (bx < 32) {
        sgemm_tile_body(inputs, W, nullptr, g_Q,
                        (bx >> 3) * 64, (bx & 7) * 64, Ddim, Ddim, As, Bs);
    } else if (bx < 40) {
        sgemm_tile_body(keys, V, Ubias, g_P, 0, (bx - 32) * 64, Ddim, Ddim, As, Bs);
    } else {
        // U -> g_UH : 64 blocks x 256 threads = 16384 (col, s) tasks
        int id = (bx - 40) * 256 + tid;
        int col = id >> 5;
        int s   = id & 31;
#pragma unroll
        for (int tg = 0; tg < 4; tg++) {
            int k = 16 * s + 2 * tg;
            unsigned short h0, l0, h1, l1, h2, l2, h3, l3;
            split_h(U[(size_t)(k + 0) * Ddim + col], h0, l0);
            split_h(U[(size_t)(k + 1) * Ddim + col], h1, l1);
            split_h(U[(size_t)(k + 8) * Ddim + col], h2, l2);
            split_h(U[(size_t)(k + 9) * Ddim + col], h3, l3);
            uint4 o;
            o.x = pack2(h0, h1);
            o.y = pack2(h2, h3);
            o.z = pack2(l0, l1);
            o.w = pack2(l2, l3);
            g_UH[((size_t)col * 32 + s) * 4 + tg] = o;
        }
    }
}

// ---------------- fused main kernel (fp16 split-3, A double-buffered in regs) ----------------
// CTA = 32 rows (one b, 32 j's) x 512 cols, 256 threads, 8 column-warps.
// Barrier-free mainloop: per-warp 3-stage B pipeline (cp.async + syncwarp only);
// A raw floats prefetched one slab ahead in registers, split in-register.
__global__ __launch_bounds__(256, 2) void fused_kernel(
    const float* __restrict__ inputs,
    const float* __restrict__ state,
    const float* __restrict__ keys,
    float* __restrict__ out)
{
    extern __shared__ char smraw[];
    uint4* Bbuf  = reinterpret_cast<uint4*>(smraw);                 // 8 x [3][64][4] uint4 = 96KB
    float* gate  = reinterpret_cast<float*>(smraw + 98304);         // [32]
    float* normv = gate + 32;                                        // [32]
    float* red   = normv + 32;                                       // [8][32]

    int tid  = threadIdx.x;
    int bx   = blockIdx.x;
    int row0 = bx * 32;
    int b    = bx >> 1;
    int j0   = (bx & 1) * 32;

    int lane = tid & 31;
    int w    = tid >> 5;
    int gid  = lane >> 2;
    int tig  = lane & 3;
    int cb   = w * 64;

    uint4* mybuf = Bbuf + w * 768;                    // [3][64][4] uint4 (12KB)
    const uint4* usrc = g_UH + (size_t)cb * 128;      // col-major: col*128 + s*4 + tg

    // per-warp prefetch of B slabs 0..2
#pragma unroll
    for (int st = 0; st < 3; st++) {
#pragma unroll
        for (int q = 0; q < 8; q++) {
            int idx = lane + 32 * q;                  // 0..255
            int col = idx >> 2, p = idx & 3;
            cp_async16(mybuf + st * 256 + idx, usrc + (size_t)col * 128 + st * 4 + p);
        }
        cp_commit();
    }

    // Gates: warp w -> rows 4w..4w+3 ; z = inputs[b].(s_row + key_j)
    {
        const float* ir = inputs + (size_t)b * Ddim;
#pragma unroll
        for (int i = 0; i < 4; i++) {
            int r = w * 4 + i;
            const float* sr = state + (size_t)(row0 + r) * Ddim;
            const float* kr = keys + (size_t)(j0 + r) * Ddim;
            float z = 0.f;
            for (int k = lane; k < Ddim; k += 32)
                z += ir[k] * (sr[k] + kr[k]);
#pragma unroll
            for (int o = 16; o; o >>= 1) z += __shfl_xor_sync(0xffffffffu, z, o);
            if (lane == 0) gate[r] = 1.f / (1.f + expf(-z));
        }
    }

    // -------- barrier-free fp16 split-3 mainloop: 32 k16-slabs --------
    float acc[2][8][4];
#pragma unroll
    for (int mi = 0; mi < 2; mi++)
#pragma unroll
        for (int nf = 0; nf < 8; nf++)
#pragma unroll
            for (int c = 0; c < 4; c++) acc[mi][nf][c] = 0.f;

    // A base: this thread covers rows row0 + gid + {0,8,16,24}, k-pairs at 2*tig and 2*tig+8
    const float* Sbase = state + (size_t)(row0 + gid) * Ddim + 2 * tig;
    int stc = 0;                                       // consume stage (s % 3)

    // preload A raw floats for slab 0
    float2 nx0[4], nx1[4];
#pragma unroll
    for (int r4 = 0; r4 < 4; r4++) {
        const float* sr = Sbase + (size_t)(8 * r4) * Ddim;
        nx0[r4] = *reinterpret_cast<const float2*>(sr);
        nx1[r4] = *reinterpret_cast<const float2*>(sr + 8);
    }

#pragma unroll 1
    for (int s = 0; s < 32; s++) {
        if (s < 30) cp_wait2(); else if (s == 30) cp_wait1(); else cp_wait0();
        __syncwarp();

        // take current A, immediately issue next slab's A loads (hidden under MMAs)
        float2 c0[4], c1[4];
#pragma unroll
        for (int r4 = 0; r4 < 4; r4++) { c0[r4] = nx0[r4]; c1[r4] = nx1[r4]; }
        if (s + 1 < 32) {
            int kn = (s + 1) * 16;
#pragma unroll
            for (int r4 = 0; r4 < 4; r4++) {
                const float* sr = Sbase + (size_t)(8 * r4) * Ddim + kn;
                nx0[r4] = *reinterpret_cast<const float2*>(sr);
                nx1[r4] = *reinterpret_cast<const float2*>(sr + 8);
            }
        }

        // split current A in registers
        unsigned ah[2][4], al[2][4];
#pragma unroll
        for (int r4 = 0; r4 < 4; r4++) {
            int mi = r4 >> 1, hr = r4 & 1;
            split2(c0[r4].x, c0[r4].y, ah[mi][hr],     al[mi][hr]);
            split2(c1[r4].x, c1[r4].y, ah[mi][hr + 2], al[mi][hr + 2]);
        }

        const uint4* Bs = mybuf + stc * 256;
#pragma unroll
        for (int half = 0; half < 2; half++) {
            uint4 bq[4];
#pragma unroll
            for (int q = 0; q < 4; q++) {
                int nf = half * 4 + q;
                bq[q] = Bs[(nf * 8 + gid) * 4 + tig];
            }
            // hh
#pragma unroll
            for (int q = 0; q < 4; q++)
#pragma unroll
                for (int mi = 0; mi < 2; mi++)
                    mma_f16(acc[mi][half * 4 + q], ah[mi], bq[q].x, bq[q].y);
            // lh
#pragma unroll
            for (int q = 0; q < 4; q++)
#pragma unroll
                for (int mi = 0; mi < 2; mi++)
                    mma_f16(acc[mi][half * 4 + q], al[mi], bq[q].x, bq[q].y);
            // hl
#pragma unroll
            for (int q = 0; q < 4; q++)
#pragma unroll
                for (int mi = 0; mi < 2; mi++)
                    mma_f16(acc[mi][half * 4 + q], ah[mi], bq[q].z, bq[q].w);
        }

        // prefetch B slab s+3 into the stage just consumed
        if (s + 3 < 32) {
            uint4* Ud = mybuf + stc * 256;
#pragma unroll
            for (int q = 0; q < 8; q++) {
                int idx = lane + 32 * q;
                int col = idx >> 2, p = idx & 3;
                cp_async16(Ud + idx, usrc + (size_t)col * 128 + (s + 3) * 4 + p);
            }
            cp_commit();
        }
        stc = (stc == 2) ? 0 : stc + 1;
    }

    __syncthreads();   // gates visible

    // -------- epilogue: v = s + g*relu(acc + Q[b] + P[j]); row-norm partials --------
    const float* Qb = g_Q + (size_t)b * Ddim;
    float part[4];
#pragma unroll
    for (int mi = 0; mi < 2; mi++) {
#pragma unroll
        for (int h = 0; h < 2; h++) {
            int r = mi * 16 + h * 8 + gid;
            float g = gate[r];
            const float* Pr = g_P + (size_t)(j0 + r) * Ddim;
            const float* Sr = state + (size_t)(row0 + r) * Ddim;
            float psum = 0.f;
#pragma unroll
            for (int nf = 0; nf < 8; nf++) {
                int c0 = cb + nf * 8 + tig * 2;
                float2 p2 = *reinterpret_cast<const float2*>(Pr + c0);
                float2 q2 = *reinterpret_cast<const float2*>(Qb + c0);
                float2 s2 = *reinterpret_cast<const float2*>(Sr + c0);
                float pre0 = acc[mi][nf][h * 2 + 0] + q2.x + p2.x;
                float pre1 = acc[mi][nf][h * 2 + 1] + q2.y + p2.y;
                float v0 = s2.x + g * fmaxf(pre0, 0.f);
                float v1 = s2.y + g * fmaxf(pre1, 0.f);
                acc[mi][nf][h * 2 + 0] = v0;
                acc[mi][nf][h * 2 + 1] = v1;
                psum += v0 * v0 + v1 * v1;
            }
            part[mi * 2 + h] = psum;
        }
    }
#pragma unroll
    for (int i = 0; i < 4; i++) {
        part[i] += __shfl_xor_sync(0xffffffffu, part[i], 1);
        part[i] += __shfl_xor_sync(0xffffffffu, part[i], 2);
    }
    if (tig == 0) {
#pragma unroll
        for (int mi = 0; mi < 2; mi++)
#pragma unroll
            for (int h = 0; h < 2; h++)
                red[w * 32 + mi * 16 + h * 8 + gid] = part[mi * 2 + h];
    }
    __syncthreads();
    if (tid < 32) {
        float sum = 0.f;
#pragma unroll
        for (int ww = 0; ww < 8; ww++) sum += red[ww * 32 + tid];
        normv[tid] = fmaxf(sqrtf(sum), 1e-12f);
    }
    __syncthreads();

    // out = (v > 0) ? norm : v
#pragma unroll
    for (int mi = 0; mi < 2; mi++) {
#pragma unroll
        for (int h = 0; h < 2; h++) {
            int r = mi * 16 + h * 8 + gid;
            float n = normv[r];
            float* orow = out + (size_t)(row0 + r) * Ddim;
#pragma unroll
            for (int nf = 0; nf < 8; nf++) {
                int c0 = cb + nf * 8 + tig * 2;
                float v0 = acc[mi][nf][h * 2 + 0];
                float v1 = acc[mi][nf][h * 2 + 1];
                float2 o;
                o.x = v0 > 0.f ? n : v0;
                o.y = v1 > 0.f ? n : v1;
                *reinterpret_cast<float2*>(orow + c0) = o;
            }
        }
    }
}

extern "C" void kernel_launch(void* const* d_in, const int* in_sizes, int n_in,
                              void* d_out, int out_size)
{
    const float* inputs = (const float*)d_in[0];
    const float* state  = (const float*)d_in[1];
    const float* keys   = (const float*)d_in[2];
    const float* U      = (const float*)d_in[3];
    const float* V      = (const float*)d_in[4];
    const float* W      = (const float*)d_in[5];
    const float* Ubias  = (const float*)d_in[6];
    float* out = (float*)d_out;
    (void)in_sizes; (void)n_in; (void)out_size;

    // Q(32) + P(8) + UH(64) = 104 blocks
    precompute_kernel<<<104, 256>>>(inputs, keys, V, W, U, Ubias);

    size_t smem = 98304 + (32 + 32 + 8 * 32) * sizeof(float);
    cudaFuncSetAttribute(fused_kernel, cudaFuncAttributeMaxDynamicSharedMemorySize, (int)smem);
    fused_kernel<<<(Bdim * Jdim) / 32, 256, smem>>>(inputs, state, keys, out);
}

// round 17
// speedup vs baseline: 1.0351x; 1.0351x over previous
#include <cuda_runtime.h>
#include <cuda_fp16.h>
#include <math.h>
#include <stdint.h>

#define Bdim 256
#define Jdim 64
#define Ddim 512

// ---- scratch (allocation-free rule: __device__ globals) ----
__device__ float g_Q[Bdim * Ddim];     // inputs @ W
__device__ float g_P[Jdim * Ddim];     // keys @ V + U_bias
// U pre-split fp16, transposed, k16-interleaved:
// g_UH[(col*32 + s)*4 + tg] = { hi2(16s+2tg,+1), hi2(16s+2tg+8,+9),
//                               lo2(16s+2tg,+1), lo2(16s+2tg+8,+9) }
__device__ uint4 g_UH[Ddim * 32 * 4];

// ---------------- cp.async helpers ----------------
__device__ __forceinline__ void cp_async16(void* smem_dst, const void* gmem_src) {
    unsigned s = (unsigned)__cvta_generic_to_shared(smem_dst);
    asm volatile("cp.async.cg.shared.global [%0], [%1], 16;\n" :: "r"(s), "l"(gmem_src));
}
__device__ __forceinline__ void cp_commit() { asm volatile("cp.async.commit_group;\n"); }
__device__ __forceinline__ void cp_wait2()  { asm volatile("cp.async.wait_group 2;\n"); }
__device__ __forceinline__ void cp_wait1()  { asm volatile("cp.async.wait_group 1;\n"); }
__device__ __forceinline__ void cp_wait0()  { asm volatile("cp.async.wait_group 0;\n"); }
__device__ __forceinline__ void named_bar(int id, int cnt) {
    asm volatile("bar.sync %0, %1;" :: "r"(id), "r"(cnt) : "memory");
}

// ---------------- fp16 split helpers ----------------
__device__ __forceinline__ void split_h(float x, unsigned short& hi, unsigned short& lo) {
    __half h = __float2half_rn(x);
    hi = __half_as_ushort(h);
    lo = __half_as_ushort(__float2half_rn(x - __half2float(h)));
}
__device__ __forceinline__ unsigned pack2(unsigned short a, unsigned short b) {
    return (unsigned)a | ((unsigned)b << 16);
}
__device__ __forceinline__ void split2(float x, float y, unsigned& hi2, unsigned& lo2) {
    __half2 h = __floats2half2_rn(x, y);
    float rx = x - __low2float(h);
    float ry = y - __high2float(h);
    __half2 l = __floats2half2_rn(rx, ry);
    hi2 = *reinterpret_cast<unsigned*>(&h);
    lo2 = *reinterpret_cast<unsigned*>(&l);
}
// D += A(16x16,row) * B(16x8,col)   (fp16 in, fp32 acc)
__device__ __forceinline__ void mma_f16(float d[4], const unsigned a[4], unsigned b0, unsigned b1) {
    asm volatile("mma.sync.aligned.m16n8k16.row.col.f32.f16.f16.f32 "
        "{%0,%1,%2,%3}, {%4,%5,%6,%7}, {%8,%9}, {%0,%1,%2,%3};"
        : "+f"(d[0]), "+f"(d[1]), "+f"(d[2]), "+f"(d[3])
        : "r"(a[0]), "r"(a[1]), "r"(a[2]), "r"(a[3]), "r"(b0), "r"(b1));
}

// ---------------- precompute: 32x64 tiles ----------------
__device__ __forceinline__ void sgemm_tile32(
    const float* __restrict__ A, const float* __restrict__ Bm,
    const float* __restrict__ bias, float* __restrict__ C,
    int m0, int n0, int N, int K,
    float (*As)[32], float (*Bs)[64])
{
    int tid = threadIdx.x;
    int ty = tid >> 4, tx = tid & 15;      // 16x16 threads; micro tile 2x4
    float acc[2][4];
#pragma unroll
    for (int i = 0; i < 2; i++)
#pragma unroll
        for (int j = 0; j < 4; j++) acc[i][j] = 0.f;

    for (int k0 = 0; k0 < K; k0 += 16) {
        {   // A tile 32x16 -> As[k][m], each thread float2
            int m  = tid >> 3;
            int kk = (tid & 7) * 2;
            float2 v = *reinterpret_cast<const float2*>(&A[(size_t)(m0 + m) * K + k0 + kk]);
            As[kk + 0][m] = v.x;
            As[kk + 1][m] = v.y;
        }
        {   // B tile 16x64
            int kk = tid >> 4, c4 = (tid & 15) * 4;
            *reinterpret_cast<float4*>(&Bs[kk][c4]) =
                *reinterpret_cast<const float4*>(&Bm[(size_t)(k0 + kk) * N + n0 + c4]);
        }
        __syncthreads();
#pragma unroll
        for (int kk = 0; kk < 16; kk++) {
            float a0 = As[kk][ty * 2 + 0];
            float a1 = As[kk][ty * 2 + 1];
            float4 b4 = *reinterpret_cast<const float4*>(&Bs[kk][tx * 4]);
            float b[4] = {b4.x, b4.y, b4.z, b4.w};
#pragma unroll
            for (int j = 0; j < 4; j++) {
                acc[0][j] += a0 * b[j];
                acc[1][j] += a1 * b[j];
            }
        }
        __syncthreads();
    }
    float bb[4] = {0.f, 0.f, 0.f, 0.f};
    if (bias) {
#pragma unroll
        for (int j = 0; j < 4; j++) bb[j] = bias[n0 + tx * 4 + j];
    }
#pragma unroll
    for (int i = 0; i < 2; i++) {
        float4 o;
        o.x = acc[i][0] + bb[0]; o.y = acc[i][1] + bb[1];
        o.z = acc[i][2] + bb[2]; o.w = acc[i][3] + bb[3];
        *reinterpret_cast<float4*>(&C[(size_t)(m0 + ty * 2 + i) * N + n0 + tx * 4]) = o;
    }
}

// blocks: [0,64) Q ; [64,80) P ; [80,144) UH
__global__ __launch_bounds__(256) void precompute_kernel(
    const float* __restrict__ inputs, const float* __restrict__ keys,
    const float* __restrict__ V, const float* __restrict__ W,
    const float* __restrict__ U, const float* __restrict__ Ubias)
{
    __shared__ float As[16][32];
    __shared__ float Bs[16][64];
    int bx = blockIdx.x, tid = threadIdx.x;
    if (bx < 64) {
        sgemm_tile32(inputs, W, nullptr, g_Q,
                     (bx >> 3) * 32, (bx & 7) * 64, Ddim, Ddim, As, Bs);
    } else if (bx < 80) {
        int t = bx - 64;
        sgemm_tile32(keys, V, Ubias, g_P,
                     (t >> 3) * 32, (t & 7) * 64, Ddim, Ddim, As, Bs);
    } else {
        // U -> g_UH : 64 blocks x 256 threads = 16384 (col, s) tasks
        int id = (bx - 80) * 256 + tid;
        int col = id >> 5;
        int s   = id & 31;
#pragma unroll
        for (int tg = 0; tg < 4; tg++) {
            int k = 16 * s + 2 * tg;
            unsigned short h0, l0, h1, l1, h2, l2, h3, l3;
            split_h(U[(size_t)(k + 0) * Ddim + col], h0, l0);
            split_h(U[(size_t)(k + 1) * Ddim + col], h1, l1);
            split_h(U[(size_t)(k + 8) * Ddim + col], h2, l2);
            split_h(U[(size_t)(k + 9) * Ddim + col], h3, l3);
            uint4 o;
            o.x = pack2(h0, h1);
            o.y = pack2(h2, h3);
            o.z = pack2(l0, l1);
            o.w = pack2(l2, l3);
            g_UH[((size_t)col * 32 + s) * 4 + tg] = o;
        }
    }
}

// ---------------- fused main kernel ----------------
// CTA = one batch element b: 64 rows (all j) x 512 cols, 512 threads, 16 warps
// = 2 row-groups (wr) x 8 col-groups (wc). The wr pair shares one B pipeline:
// wr=0 warp produces (cp.async, 4 stages), both consume.
// Pair sync = named barrier id wc+1 (id 0 reserved for __syncthreads).
__global__ __launch_bounds__(512, 1) void fused_kernel(
    const float* __restrict__ inputs,
    const float* __restrict__ state,
    const float* __restrict__ keys,
    float* __restrict__ out)
{
    extern __shared__ char smraw[];
    uint4* Bbuf  = reinterpret_cast<uint4*>(smraw);                 // 8 wc x [4][64][4] uint4 = 128KB
    float* gate  = reinterpret_cast<float*>(smraw + 131072);        // [64]
    float* normv = gate + 64;                                        // [64]
    float* red   = normv + 64;                                       // [8][64]

    int tid  = threadIdx.x;
    int bx   = blockIdx.x;                 // = b
    int row0 = bx * 64;

    int lane = tid & 31;
    int w    = tid >> 5;                   // 0..15
    int wc   = w & 7;                      // column group
    int wr   = w >> 3;                     // row group (0/1)
    int gid  = lane >> 2;
    int tig  = lane & 3;
    int cb   = wc * 64;

    uint4* mybuf = Bbuf + wc * 1024;       // [4][64][4] uint4 (16KB per pair)
    const uint4* usrc = g_UH + (size_t)cb * 128;   // col*128 + s*4 + tg

    // producer prologue: slabs 0..2 into stages 0..2
    if (wr == 0) {
#pragma unroll
        for (int st = 0; st < 3; st++) {
#pragma unroll
            for (int q = 0; q < 8; q++) {
                int idx = lane + 32 * q;
                int col = idx >> 2, p = idx & 3;
                cp_async16(mybuf + st * 256 + idx, usrc + (size_t)col * 128 + st * 4 + p);
            }
            cp_commit();
        }
    }

    // Gates: warp w -> rows 4w..4w+3 ; z = inputs[b].(s_row + key_j), j = r
    {
        const float* ir = inputs + (size_t)bx * Ddim;
#pragma unroll
        for (int i = 0; i < 4; i++) {
            int r = w * 4 + i;
            const float* sr = state + (size_t)(row0 + r) * Ddim;
            const float* kr = keys + (size_t)r * Ddim;
            float z = 0.f;
            for (int k = lane; k < Ddim; k += 32)
                z += ir[k] * (sr[k] + kr[k]);
#pragma unroll
            for (int o = 16; o; o >>= 1) z += __shfl_xor_sync(0xffffffffu, z, o);
            if (lane == 0) gate[r] = 1.f / (1.f + expf(-z));
        }
    }

    // -------- fp16 split-3 mainloop: 32 k16-slabs, pairwise-shared B --------
    float acc[2][8][4];
#pragma unroll
    for (int mi = 0; mi < 2; mi++)
#pragma unroll
        for (int nf = 0; nf < 8; nf++)
#pragma unroll
            for (int c = 0; c < 4; c++) acc[mi][nf][c] = 0.f;

    // A rows: this warp covers rows wr*32 + {gid, gid+8, gid+16, gid+24}
    const float* Sbase = state + (size_t)(row0 + wr * 32 + gid) * Ddim + 2 * tig;

#pragma unroll 1
    for (int s = 0; s < 32; s++) {
        if (wr == 0) {
            if (s < 30) cp_wait2(); else if (s == 30) cp_wait1(); else cp_wait0();
        }
        named_bar(wc + 1, 64);             // stage s ready; pair done with s-1

        int k0 = s * 16;
        // A fragments: 8 x LDG.64 fp32 + in-register fp16 hi/lo split
        unsigned ah[2][4], al[2][4];
#pragma unroll
        for (int r4 = 0; r4 < 4; r4++) {
            const float* sr = Sbase + (size_t)(8 * r4) * Ddim + k0;
            float2 p0 = *reinterpret_cast<const float2*>(sr);
            float2 p1 = *reinterpret_cast<const float2*>(sr + 8);
            int mi = r4 >> 1, hr = r4 & 1;
            split2(p0.x, p0.y, ah[mi][hr],     al[mi][hr]);
            split2(p1.x, p1.y, ah[mi][hr + 2], al[mi][hr + 2]);
        }

        const uint4* Bs = mybuf + (s & 3) * 256;
#pragma unroll
        for (int half = 0; half < 2; half++) {
            uint4 bq[4];
#pragma unroll
            for (int q = 0; q < 4; q++) {
                int nf = half * 4 + q;
                bq[q] = Bs[(nf * 8 + gid) * 4 + tig];
            }
            // hh
#pragma unroll
            for (int q = 0; q < 4; q++)
#pragma unroll
                for (int mi = 0; mi < 2; mi++)
                    mma_f16(acc[mi][half * 4 + q], ah[mi], bq[q].x, bq[q].y);
            // lh
#pragma unroll
            for (int q = 0; q < 4; q++)
#pragma unroll
                for (int mi = 0; mi < 2; mi++)
                    mma_f16(acc[mi][half * 4 + q], al[mi], bq[q].x, bq[q].y);
            // hl
#pragma unroll
            for (int q = 0; q < 4; q++)
#pragma unroll
                for (int mi = 0; mi < 2; mi++)
                    mma_f16(acc[mi][half * 4 + q], ah[mi], bq[q].z, bq[q].w);
        }

        // producer prefetch slab s+3 into stage (s+3)&3 (freed: pair finished s-1)
        if (wr == 0 && s + 3 < 32) {
            uint4* Ud = mybuf + ((s + 3) & 3) * 256;
#pragma unroll
            for (int q = 0; q < 8; q++) {
                int idx = lane + 32 * q;
                int col = idx >> 2, p = idx & 3;
                cp_async16(Ud + idx, usrc + (size_t)col * 128 + (s + 3) * 4 + p);
            }
            cp_commit();
        }
    }

    __syncthreads();   // gates visible

    // -------- epilogue: v = s + g*relu(acc + Q[b] + P[j]); row-norm partials --------
    const float* Qb = g_Q + (size_t)bx * Ddim;
    float part[4];
#pragma unroll
    for (int mi = 0; mi < 2; mi++) {
#pragma unroll
        for (int h = 0; h < 2; h++) {
            int r = wr * 32 + mi * 16 + h * 8 + gid;      // 0..63, j = r
            float g = gate[r];
            const float* Pr = g_P + (size_t)r * Ddim;
            const float* Sr = state + (size_t)(row0 + r) * Ddim;
            float psum = 0.f;
#pragma unroll
            for (int nf = 0; nf < 8; nf++) {
                int c0 = cb + nf * 8 + tig * 2;
                float2 p2 = *reinterpret_cast<const float2*>(Pr + c0);
                float2 q2 = *reinterpret_cast<const float2*>(Qb + c0);
                float2 s2 = *reinterpret_cast<const float2*>(Sr + c0);
                float pre0 = acc[mi][nf][h * 2 + 0] + q2.x + p2.x;
                float pre1 = acc[mi][nf][h * 2 + 1] + q2.y + p2.y;
                float v0 = s2.x + g * fmaxf(pre0, 0.f);
                float v1 = s2.y + g * fmaxf(pre1, 0.f);
                acc[mi][nf][h * 2 + 0] = v0;
                acc[mi][nf][h * 2 + 1] = v1;
                psum += v0 * v0 + v1 * v1;
            }
            part[mi * 2 + h] = psum;
        }
    }
#pragma unroll
    for (int i = 0; i < 4; i++) {
        part[i] += __shfl_xor_sync(0xffffffffu, part[i], 1);
        part[i] += __shfl_xor_sync(0xffffffffu, part[i], 2);
    }
    if (tig == 0) {
#pragma unroll
        for (int mi = 0; mi < 2; mi++)
#pragma unroll
            for (int h = 0; h < 2; h++)
                red[wc * 64 + wr * 32 + mi * 16 + h * 8 + gid] = part[mi * 2 + h];
    }
    __syncthreads();
    if (tid < 64) {
        float sum = 0.f;
#pragma unroll
        for (int ww = 0; ww < 8; ww++) sum += red[ww * 64 + tid];
        normv[tid] = fmaxf(sqrtf(sum), 1e-12f);
    }
    __syncthreads();

    // out = (v > 0) ? norm : v
#pragma unroll
    for (int mi = 0; mi < 2; mi++) {
#pragma unroll
        for (int h = 0; h < 2; h++) {
            int r = wr * 32 + mi * 16 + h * 8 + gid;
            float n = normv[r];
            float* orow = out + (size_t)(row0 + r) * Ddim;
#pragma unroll
            for (int nf = 0; nf < 8; nf++) {
                int c0 = cb + nf * 8 + tig * 2;
                float v0 = acc[mi][nf][h * 2 + 0];
                float v1 = acc[mi][nf][h * 2 + 1];
                float2 o;
                o.x = v0 > 0.f ? n : v0;
                o.y = v1 > 0.f ? n : v1;
                *reinterpret_cast<float2*>(orow + c0) = o;
            }
        }
    }
}

extern "C" void kernel_launch(void* const* d_in, const int* in_sizes, int n_in,
                              void* d_out, int out_size)
{
    const float* inputs = (const float*)d_in[0];
    const float* state  = (const float*)d_in[1];
    const float* keys   = (const float*)d_in[2];
    const float* U      = (const float*)d_in[3];
    const float* V      = (const float*)d_in[4];
    const float* W      = (const float*)d_in[5];
    const float* Ubias  = (const float*)d_in[6];
    float* out = (float*)d_out;
    (void)in_sizes; (void)n_in; (void)out_size;

    // Q(64) + P(16) + UH(64) = 144 blocks
    precompute_kernel<<<144, 256>>>(inputs, keys, V, W, U, Ubias);

    size_t smem = 131072 + (64 + 64 + 8 * 64) * sizeof(float);
    cudaFuncSetAttribute(fused_kernel, cudaFuncAttributeMaxDynamicSharedMemorySize, (int)smem);
    fused_kernel<<<Bdim, 512, smem>>>(inputs, state, keys, out);
}